// round 16
// baseline (speedup 1.0000x reference)
#include <cuda_runtime.h>
#include <cuda_fp16.h>
#include <math.h>
#include <cstdint>

// Problem constants (V2VNet_35373350650590):
// B=2, A=5, C=64, H=W=128, gnn_iter=2
#define NB   2
#define NA   5
#define BA   10      // B*A
#define NC   64
#define NCP  32      // channel pairs
#define HH   128
#define WW   128
#define HW   16384   // H*W
#define NO   192     // 3*C output channels of gate conv
#define KK   1152    // 2C * 9 reduction dim

// ---------------- static scratch (no allocations allowed) ----------------
// half2 channel-pair-interleaved planes: [n][cp][h][w], one uint32 = (ch 2cp, 2cp+1)
__device__ uint32_t g_fh2a[(size_t)BA * NCP * HW];  // 21 MB (iter0 input)
__device__ uint32_t g_fh2b[(size_t)BA * NCP * HW];  // 21 MB (iter0 out / iter1 in)
__device__ uint32_t g_mh2 [(size_t)BA * NCP * HW];  // 21 MB (mean)
__device__ __half   g_wt  [(size_t)NO * KK];        // fp16 weights, permuted

// ======================= PTX helpers (portable) ==========================
__device__ __forceinline__ uint32_t smem_to_u32(const void* p) {
    uint32_t a;
    asm("{ .reg .u64 t; cvta.to.shared.u64 t, %1; cvt.u32.u64 %0, t; }"
        : "=r"(a) : "l"(p));
    return a;
}
#define LDMATRIX_X4(r0, r1, r2, r3, addr) \
    asm volatile("ldmatrix.sync.aligned.m8n8.x4.shared.b16 {%0,%1,%2,%3}, [%4];" \
        : "=r"(r0), "=r"(r1), "=r"(r2), "=r"(r3) : "r"(addr))
#define MMA16816(c, a, b0, b1) \
    asm volatile("mma.sync.aligned.m16n8k16.row.col.f32.f16.f16.f32 " \
        "{%0,%1,%2,%3}, {%4,%5,%6,%7}, {%8,%9}, {%0,%1,%2,%3};" \
        : "+f"((c)[0]), "+f"((c)[1]), "+f"((c)[2]), "+f"((c)[3]) \
        : "r"((a)[0]), "r"((a)[1]), "r"((a)[2]), "r"((a)[3]), \
          "r"(b0), "r"(b1))
#define STS32(addr, v) \
    asm volatile("st.shared.b32 [%0], %1;" :: "r"(addr), "r"(v) : "memory")
#define CP_ASYNC4(dst, src, sz) \
    asm volatile("cp.async.ca.shared.global [%0], [%1], 4, %2;" \
        :: "r"(dst), "l"(src), "r"(sz) : "memory")
#define CP_ASYNC16(dst, src) \
    asm volatile("cp.async.cg.shared.global [%0], [%1], 16;" \
        :: "r"(dst), "l"(src) : "memory")
#define CP_COMMIT() asm volatile("cp.async.commit_group;" ::: "memory")
#define CP_WAIT_GROUP(n) \
    asm volatile("cp.async.wait_group %0;" :: "n"(n) : "memory")
#define BAR_SYNC(id, cnt) \
    asm volatile("bar.sync %0, %1;" :: "r"(id), "r"(cnt) : "memory")

// =========================================================================
// Kernel 0a: weight permute + fp16 round.
// row' = (ch>>4)*48 + gate*16 + (ch&15); K tap-major: k' = tap*128 + cc.
// =========================================================================
__global__ __launch_bounds__(256)
void wtrans_kernel(const float* __restrict__ wx, __half* __restrict__ wt)
{
    int idx = blockIdx.x * 256 + threadIdx.x;
    if (idx >= NO * KK) return;
    int rowp = idx / KK;
    int kp   = idx - rowp * KK;
    int wn   = rowp / 48;
    int rem  = rowp - wn * 48;
    int gate = rem >> 4;
    int chl  = rem & 15;
    int o    = gate * 64 + wn * 16 + chl;
    int tap  = kp >> 7;
    int cc   = kp & 127;
    wt[idx] = __float2half_rn(wx[o * KK + cc * 9 + tap]);
}

// =========================================================================
// Kernel 0b: pack fp32 feats -> half2 channel-pair planes.
// =========================================================================
__global__ __launch_bounds__(256)
void cvt_kernel(const float* __restrict__ feats, uint32_t* __restrict__ fh2)
{
    int idx = blockIdx.x * 256 + threadIdx.x;   // < BA*NCP*HW
    int n   = idx >> 19;                        // / (NCP*HW)
    int cp  = (idx >> 14) & 31;
    int pix = idx & 16383;
    float f0 = feats[(((size_t)n * NC + 2 * cp)     << 14) + pix];
    float f1 = feats[(((size_t)n * NC + 2 * cp + 1) << 14) + pix];
    __half2 h = __floats2half2_rn(f0, f1);
    fh2[idx] = *(uint32_t*)&h;
}

// =========================================================================
// Kernel 1: warp (rotate then translate resample) + masked mean, half2.
// One CTA per (bi, cpair). Zero-border 131x131 planes; coords clamped to
// [-1,128] (exact zero-pad semantics). half2 bilinear lerp (R15).
// NEW: 1024 threads/CTA (was 512). smem caps the SM at 1 CTA either way,
// so doubling warps doubles occupancy (25% -> 50%) for this
// latency/issue-bound kernel. Per-pixel math and j-order identical.
// =========================================================================
#define SW 131
__global__ __launch_bounds__(1024, 1)
void warp_mean_kernel(const uint32_t* __restrict__ fh2,
                      const float* __restrict__ trans,
                      uint32_t* __restrict__ mh2)
{
    const int cp = blockIdx.x;      // 0..31
    const int bi = blockIdx.y;      // 0..9
    const int b  = bi / NA;
    const int i  = bi - b * NA;

    extern __shared__ uint32_t smu[];
    uint32_t* s_src = smu;              // SW*SW half2
    uint32_t* s_f   = smu + SW * SW;    // SW*SW half2

    const int tid = threadIdx.x;

    for (int v = tid; v < 2 * SW * SW; v += 1024) smu[v] = 0u;
    __syncthreads();

    float accx[16], accy[16];
#pragma unroll
    for (int k = 0; k < 16; k++) { accx[k] = 0.f; accy[k] = 0.f; }

    for (int j = 0; j < NA; j++) {
        if (j == i) continue;
        const float* tp = trans + (size_t)(bi * NA + j) * 16;
        const float t00 = tp[0], t01 = tp[1], t03 = tp[3];
        const float t10 = tp[4], t11 = tp[5], t13 = tp[7];

        const uint32_t* src = fh2 + (((size_t)(b * NA + j) * NCP + cp) << 14);
#pragma unroll
        for (int v = tid; v < HW / 4; v += 1024) {
            uint4 x = ((const uint4*)src)[v];
            int r  = v >> 5;
            int c4 = (v & 31) << 2;
            uint32_t* d = s_src + (r + 1) * SW + c4 + 1;
            d[0] = x.x; d[1] = x.y; d[2] = x.z; d[3] = x.w;
        }
        __syncthreads();

        // ---- pass 1: rotation resample (half2 lerp) ----
#pragma unroll 4
        for (int k = 0; k < 16; k++) {
            int p = tid + (k << 10);
            int h = p >> 7, w = p & 127;
            float wf = (float)w - 63.5f;
            float hf = (float)h - 63.5f;
            float px = fmaf(t00, wf, fmaf(t01, hf, 63.5f));
            float py = fmaf(t10, wf, fmaf(t11, hf, 63.5f));
            px = fminf(fmaxf(px, -1.f), 128.f);
            py = fminf(fmaxf(py, -1.f), 128.f);
            float x0f = floorf(px), y0f = floorf(py);
            float fx = px - x0f, fy = py - y0f;
            int base = ((int)y0f + 1) * SW + (int)x0f + 1;
            __half2 a00 = *(__half2*)&s_src[base];
            __half2 a10 = *(__half2*)&s_src[base + 1];
            __half2 a01 = *(__half2*)&s_src[base + SW];
            __half2 a11 = *(__half2*)&s_src[base + SW + 1];
            __half2 hfx = __float2half2_rn(fx);
            __half2 hgx = __float2half2_rn(1.f - fx);
            __half2 hfy = __float2half2_rn(fy);
            __half2 hgy = __float2half2_rn(1.f - fy);
            __half2 t0 = __hfma2(a10, hfx, __hmul2(a00, hgx));
            __half2 t1 = __hfma2(a11, hfx, __hmul2(a01, hgx));
            __half2 r  = __hfma2(t1, hfy, __hmul2(t0, hgy));
            s_f[(h + 1) * SW + w + 1] = *(uint32_t*)&r;
        }
        __syncthreads();

        // ---- pass 2: constant-shift translate resample, fp32 accumulate ----
        const float tx = 2.f * t03;
        const float ty = -2.f * t13;
#pragma unroll 4
        for (int k = 0; k < 16; k++) {
            int p = tid + (k << 10);
            int h = p >> 7, w = p & 127;
            float px = fminf(fmaxf((float)w + tx, -1.f), 128.f);
            float py = fminf(fmaxf((float)h + ty, -1.f), 128.f);
            float x0f = floorf(px), y0f = floorf(py);
            float fx = px - x0f, fy = py - y0f;
            int base = ((int)y0f + 1) * SW + (int)x0f + 1;
            __half2 a00 = *(__half2*)&s_f[base];
            __half2 a10 = *(__half2*)&s_f[base + 1];
            __half2 a01 = *(__half2*)&s_f[base + SW];
            __half2 a11 = *(__half2*)&s_f[base + SW + 1];
            __half2 hfx = __float2half2_rn(fx);
            __half2 hgx = __float2half2_rn(1.f - fx);
            __half2 hfy = __float2half2_rn(fy);
            __half2 hgy = __float2half2_rn(1.f - fy);
            __half2 t0 = __hfma2(a10, hfx, __hmul2(a00, hgx));
            __half2 t1 = __hfma2(a11, hfx, __hmul2(a01, hgx));
            __half2 r  = __hfma2(t1, hfy, __hmul2(t0, hgy));
            float2 rf = __half22float2(r);
            accx[k] += rf.x;
            accy[k] += rf.y;
        }
        __syncthreads();
    }

    uint32_t* out = mh2 + (((size_t)bi * NCP + cp) << 14);
#pragma unroll
    for (int k = 0; k < 16; k++) {
        __half2 h = __floats2half2_rn(accx[k] * 0.25f, accy[k] * 0.25f);
        out[tid + (k << 10)] = *(uint32_t*)&h;
    }
}

// =========================================================================
// Kernel 2: conv implicit GEMM (fp16 mma.sync) + fused ConvGRU gating.
// (R15 exactly: static A band + per-group B streaming + named barriers +
// fast-exp epilogue; tensor 55.2%.)
// =========================================================================
#define BANDW    130
#define BAND_PXB 256u                       // bytes per (hh,ww): 64 cp * 4
#define BAND_HS  (BANDW * BAND_PXB)         // 33280
#define BAND_SZ  (4u * BAND_HS)             // 133120
#define BROW     144u                       // 128B of halves + 16B pad
#define BTILE    (192u * BROW)              // 27648
#define NSLOT    3
#define CONV_SMEM ((int)(BAND_SZ + NSLOT * BTILE))   // 216064

__global__ __launch_bounds__(512, 1)
void conv_gate_kernel(const uint32_t* __restrict__ fh2,
                      const uint32_t* __restrict__ mh2,
                      const __half* __restrict__ wt,
                      const float* __restrict__ bx,
                      const float* __restrict__ bh,
                      float* __restrict__ outf,
                      uint32_t* __restrict__ outh2,
                      int final_iter)
{
    extern __shared__ char smemraw[];
    const uint32_t sbase = smem_to_u32(smemraw);
    const uint32_t bring = sbase + BAND_SZ;

    const int tid  = threadIdx.x;
    const int wid  = tid >> 5;
    const int lane = tid & 31;
    const int rp = blockIdx.x;        // row pair 0..63
    const int n  = blockIdx.y;        // image 0..9
    const int h0 = rp * 2;

    const int wm = wid & 3;           // m-warp: rows (wm>>1), w-half (wm&1)
    const int wn = wid >> 2;          // n-warp: channel block wn*16 (group id)
    const int gt = tid & 127;         // thread id within warp group

    float c[4][6][4];
#pragma unroll
    for (int mt = 0; mt < 4; mt++)
#pragma unroll
        for (int nt = 0; nt < 6; nt++)
#pragma unroll
            for (int r = 0; r < 4; r++) c[mt][nt][r] = 0.f;

    // ---------------- band fill (once) ----------------
    {
        int bhh = tid >> 7;                 // 0..3
        int ww  = ((tid >> 6) & 1) ? 129 : 0;
        int cc  = tid & 63;
        uint32_t dst = sbase + bhh * BAND_HS + (uint32_t)ww * BAND_PXB
                     + ((uint32_t)((cc >> 2) ^ (ww & 7)) << 4) + ((cc & 3) << 2);
        STS32(dst, 0u);
    }
    {
        const int wwt  = tid & 127;         // pixel w (=ww-1)
        const int csub = tid >> 7;          // 0..3
        const int ww   = wwt + 1;
        const uint32_t wsw = (uint32_t)(ww & 7);
#pragma unroll
        for (int bhh = 0; bhh < 4; bhh++) {
            const int gh  = h0 - 1 + bhh;
            const bool hok = ((unsigned)gh < 128u);
            const int ghc = hok ? gh : 0;
            const uint32_t sz = hok ? 4u : 0u;
            const uint32_t dst0 = sbase + bhh * BAND_HS + (uint32_t)ww * BAND_PXB;
#pragma unroll
            for (int cg = 0; cg < 16; cg++) {
                const int cc = cg * 4 + csub;          // 0..63
                const uint32_t* src = (cc < 32)
                    ? (fh2 + (((size_t)n * NCP + cc)      << 14))
                    : (mh2 + (((size_t)n * NCP + cc - 32) << 14));
                uint32_t dst = dst0 + (((uint32_t)cg ^ wsw) << 4) + (csub << 2);
                CP_ASYNC4(dst, src + (ghc << 7) + wwt, sz);
            }
        }
    }

    // ---------------- B stage loader: group wn loads its own 48 rows ----
    auto prefetch_B = [&](int s, uint32_t slot) {
        const int tap = s >> 1;
        const int hs  = s & 1;
        const __half* wb = wt + tap * 128 + hs * 64;
#pragma unroll
        for (int i = 0; i < 3; i++) {
            int idx = gt + (i << 7);        // 0..383 = 48 rows * 8 chunks
            int ol = idx >> 3, q = idx & 7;
            int o  = wn * 48 + ol;
            CP_ASYNC16(slot + o * BROW + q * 16, wb + (size_t)o * KK + q * 8);
        }
    };

    // ---------------- MMA stage ----------------
    const int lm = lane & 15;
    const int lk = lane >> 4;
    const int b_row  = (lane & 7) + ((lane >> 4) << 3);
    const int b_koff = ((lane >> 3) & 1) * 16;

    auto do_mma = [&](int s, uint32_t slot) {
        const int tap = s >> 1;
        const int ty  = tap / 3;
        const int dy  = ty - 1;
        const int dx  = tap - ty * 3 - 1;
        const int cb  = (s & 1) * 8;        // chunk base within pixel entry

        const int ww  = (wm & 1) * 64 + lm + dx + 1;
        const uint32_t w7 = (uint32_t)(ww & 7);
        const uint32_t abase = sbase
            + (uint32_t)((wm >> 1) + dy + 1) * BAND_HS
            + (uint32_t)ww * BAND_PXB;
        const uint32_t bb = slot + (uint32_t)(wn * 48 + b_row) * BROW + b_koff;

#pragma unroll
        for (int ks = 0; ks < 4; ks++) {
            uint32_t bf[3][4];
#pragma unroll
            for (int bt = 0; bt < 3; bt++)
                LDMATRIX_X4(bf[bt][0], bf[bt][1], bf[bt][2], bf[bt][3],
                            bb + bt * (16 * BROW) + ks * 32);
            const uint32_t koff =
                ((uint32_t)(cb + ks * 2 + lk) ^ w7) << 4;
            // A fragments double-buffered across mt
            uint32_t a[2][4];
            LDMATRIX_X4(a[0][0], a[0][1], a[0][2], a[0][3], abase + koff);
#pragma unroll
            for (int mt = 0; mt < 4; mt++) {
                const int cur = mt & 1, nxt = cur ^ 1;
                if (mt < 3)
                    LDMATRIX_X4(a[nxt][0], a[nxt][1], a[nxt][2], a[nxt][3],
                                abase + (mt + 1) * (16 * 256) + koff);
#pragma unroll
                for (int nt = 0; nt < 6; nt++)
                    MMA16816(c[mt][nt], a[cur],
                             bf[nt >> 1][(nt & 1) * 2],
                             bf[nt >> 1][(nt & 1) * 2 + 1]);
            }
        }
    };

    // ---------------- pipeline: band + 2-deep per-group B prefetch ------
    prefetch_B(0, bring);                 CP_COMMIT();   // g0 = band + B0
    prefetch_B(1, bring + BTILE);         CP_COMMIT();   // g1 = B1
    CP_WAIT_GROUP(1);
    __syncthreads();                      // band visible CTA-wide; B0 done

    for (int s = 0; s < 18; s++) {
        if (s + 2 < 18)
            prefetch_B(s + 2, bring + (uint32_t)((s + 2) % 3) * BTILE);
        CP_COMMIT();                      // uniform per-thread group count
        do_mma(s, bring + (uint32_t)(s % 3) * BTILE);
        CP_WAIT_GROUP(1);
        BAR_SYNC(1 + wn, 128);            // group-scope rendezvous only
    }

    // ---------------- epilogue: gate in registers, store ----------------
    const int cw = lane >> 2;
    const int cn = (lane & 3) * 2;        // even channel of the owned pair
    const int r  = wm >> 1;
    const int h  = h0 + r;
    const int wbase = (wm & 1) * 64;
#pragma unroll
    for (int half = 0; half < 2; half++) {
        const int ch0 = wn * 16 + half * 8 + cn;      // even
        float bxr[2], bxz[2], bxn[2], bhn[2];
#pragma unroll
        for (int q = 0; q < 2; q++) {
            const int ch = ch0 + q;
            bxr[q] = bx[ch]       + bh[ch];
            bxz[q] = bx[ch + 64]  + bh[ch + 64];
            bxn[q] = bx[ch + 128];
            bhn[q] = bh[ch + 128];
        }
#pragma unroll
        for (int mt = 0; mt < 4; mt++) {
#pragma unroll
            for (int rr = 0; rr < 2; rr++) {
                const int w = wbase + mt * 16 + cw + rr * 8;
                float o01[2];
#pragma unroll
                for (int q = 0; q < 2; q++) {
                    const int k = rr * 2 + q;
                    float xr = c[mt][0 + half][k];
                    float xz = c[mt][2 + half][k];
                    float xn = c[mt][4 + half][k];
                    float rg = __fdividef(1.f, 1.f + __expf(-(xr + bxr[q])));
                    float zg = __fdividef(1.f, 1.f + __expf(-(xz + bxz[q])));
                    float e2 = __expf(-2.f * (xn + bxn[q] + rg * bhn[q]));
                    float ng = __fdividef(1.f - e2, 1.f + e2);
                    o01[q] = (1.f - zg) * ng;
                }
                if (final_iter) {
                    outf[(((size_t)n * NC + ch0)     << 14) + (h << 7) + w] = o01[0];
                    outf[(((size_t)n * NC + ch0 + 1) << 14) + (h << 7) + w] = o01[1];
                } else {
                    __half2 hp = __floats2half2_rn(o01[0], o01[1]);
                    outh2[(((size_t)n * NCP + (ch0 >> 1)) << 14) + (h << 7) + w]
                        = *(uint32_t*)&hp;
                }
            }
        }
    }
}

// =========================================================================
extern "C" void kernel_launch(void* const* d_in, const int* in_sizes, int n_in,
                              void* d_out, int out_size)
{
    const float* feats = (const float*)d_in[0];   // [2,5,64,128,128]
    const float* trans = (const float*)d_in[1];   // [2,5,5,4,4]
    const float* wx    = (const float*)d_in[2];   // [192,128,3,3]
    const float* bx    = (const float*)d_in[4];   // [192]
    const float* bh    = (const float*)d_in[5];   // [192]
    float* out = (float*)d_out;                   // [2,5,64,128,128]

    uint32_t *pa, *pb, *pm;
    __half* pw;
    cudaGetSymbolAddress((void**)&pa, g_fh2a);
    cudaGetSymbolAddress((void**)&pb, g_fh2b);
    cudaGetSymbolAddress((void**)&pm, g_mh2);
    cudaGetSymbolAddress((void**)&pw, g_wt);

    const int smem1 = 2 * SW * SW * (int)sizeof(uint32_t);   // 137288
    cudaFuncSetAttribute(warp_mean_kernel,
                         cudaFuncAttributeMaxDynamicSharedMemorySize, smem1);
    cudaFuncSetAttribute(conv_gate_kernel,
                         cudaFuncAttributeMaxDynamicSharedMemorySize, CONV_SMEM);

    wtrans_kernel<<<(NO * KK + 255) / 256, 256>>>(wx, pw);
    cvt_kernel<<<(BA * NCP * HW) / 256, 256>>>(feats, pa);

    for (int it = 0; it < 2; it++) {
        const uint32_t* fin = (it == 0) ? pa : pb;
        warp_mean_kernel<<<dim3(NCP, BA), 1024, smem1>>>(fin, trans, pm);
        conv_gate_kernel<<<dim3(HH / 2, BA), 512, CONV_SMEM>>>(
            fin, pm, pw, bx, bh, out, pb, (it == 1) ? 1 : 0);
    }
}

// round 17
// speedup vs baseline: 1.5529x; 1.5529x over previous
#include <cuda_runtime.h>
#include <cuda_fp16.h>
#include <math.h>
#include <cstdint>

// Problem constants (V2VNet_35373350650590):
// B=2, A=5, C=64, H=W=128, gnn_iter=2
#define NB   2
#define NA   5
#define BA   10      // B*A
#define NC   64
#define NCP  32      // channel pairs
#define HH   128
#define WW   128
#define HW   16384   // H*W
#define NO   192     // 3*C output channels of gate conv
#define KK   1152    // 2C * 9 reduction dim

// ---------------- static scratch (no allocations allowed) ----------------
// half2 channel-pair-interleaved planes: [n][cp][h][w], one uint32 = (ch 2cp, 2cp+1)
__device__ uint32_t g_fh2a[(size_t)BA * NCP * HW];  // 21 MB (iter0 input)
__device__ uint32_t g_fh2b[(size_t)BA * NCP * HW];  // 21 MB (iter0 out / iter1 in)
__device__ uint32_t g_mh2 [(size_t)BA * NCP * HW];  // 21 MB (mean)
__device__ __half   g_wt  [(size_t)NO * KK];        // fp16 weights, permuted

// ======================= PTX helpers (portable) ==========================
__device__ __forceinline__ uint32_t smem_to_u32(const void* p) {
    uint32_t a;
    asm("{ .reg .u64 t; cvta.to.shared.u64 t, %1; cvt.u32.u64 %0, t; }"
        : "=r"(a) : "l"(p));
    return a;
}
#define LDMATRIX_X4(r0, r1, r2, r3, addr) \
    asm volatile("ldmatrix.sync.aligned.m8n8.x4.shared.b16 {%0,%1,%2,%3}, [%4];" \
        : "=r"(r0), "=r"(r1), "=r"(r2), "=r"(r3) : "r"(addr))
#define MMA16816(c, a, b0, b1) \
    asm volatile("mma.sync.aligned.m16n8k16.row.col.f32.f16.f16.f32 " \
        "{%0,%1,%2,%3}, {%4,%5,%6,%7}, {%8,%9}, {%0,%1,%2,%3};" \
        : "+f"((c)[0]), "+f"((c)[1]), "+f"((c)[2]), "+f"((c)[3]) \
        : "r"((a)[0]), "r"((a)[1]), "r"((a)[2]), "r"((a)[3]), \
          "r"(b0), "r"(b1))
#define STS32(addr, v) \
    asm volatile("st.shared.b32 [%0], %1;" :: "r"(addr), "r"(v) : "memory")
#define CP_ASYNC4(dst, src, sz) \
    asm volatile("cp.async.ca.shared.global [%0], [%1], 4, %2;" \
        :: "r"(dst), "l"(src), "r"(sz) : "memory")
#define CP_ASYNC16(dst, src) \
    asm volatile("cp.async.cg.shared.global [%0], [%1], 16;" \
        :: "r"(dst), "l"(src) : "memory")
#define CP_COMMIT() asm volatile("cp.async.commit_group;" ::: "memory")
#define CP_WAIT_GROUP(n) \
    asm volatile("cp.async.wait_group %0;" :: "n"(n) : "memory")
#define BAR_SYNC(id, cnt) \
    asm volatile("bar.sync %0, %1;" :: "r"(id), "r"(cnt) : "memory")

// =========================================================================
// Kernel 0: combined prep — blocks [0, CVT_BLOCKS) pack fp32 feats into
// half2 channel-pair planes; blocks [CVT_BLOCKS, ..) permute + fp16-round
// the conv weights (row' = (ch>>4)*48 + gate*16 + (ch&15); K tap-major).
// =========================================================================
#define CVT_BLOCKS ((BA * NCP * HW) / 256)          // 20480
#define WT_BLOCKS  ((NO * KK + 255) / 256)          // 864

__global__ __launch_bounds__(256)
void prep_kernel(const float* __restrict__ feats, uint32_t* __restrict__ fh2,
                 const float* __restrict__ wx, __half* __restrict__ wt)
{
    if (blockIdx.x < CVT_BLOCKS) {
        int idx = blockIdx.x * 256 + threadIdx.x;   // < BA*NCP*HW
        int n   = idx >> 19;                        // / (NCP*HW)
        int cp  = (idx >> 14) & 31;
        int pix = idx & 16383;
        float f0 = feats[(((size_t)n * NC + 2 * cp)     << 14) + pix];
        float f1 = feats[(((size_t)n * NC + 2 * cp + 1) << 14) + pix];
        __half2 h = __floats2half2_rn(f0, f1);
        fh2[idx] = *(uint32_t*)&h;
    } else {
        int idx = (blockIdx.x - CVT_BLOCKS) * 256 + threadIdx.x;
        if (idx >= NO * KK) return;
        int rowp = idx / KK;
        int kp   = idx - rowp * KK;
        int wn   = rowp / 48;
        int rem  = rowp - wn * 48;
        int gate = rem >> 4;
        int chl  = rem & 15;
        int o    = gate * 64 + wn * 16 + chl;
        int tap  = kp >> 7;
        int cc   = kp & 127;
        wt[idx] = __float2half_rn(wx[o * KK + cc * 9 + tap]);
    }
}

// =========================================================================
// Kernel 1: warp (rotate then translate resample) + masked mean, half2.
// One CTA per (bi, cpair), 512 threads (R15 sweet spot: 68 regs, no spill).
// Zero-border 131x131 planes; coords clamped to [-1,128] (exact zero-pad).
// half2 bilinear lerp; pass2 accumulates fp32.
// NEW vs R15: only the BORDER cells are zeroed (rows {0,129,130} full,
// cols {0,129,130} for rows 1..128) — interiors are fully overwritten
// before every read, so full-plane zeroing was wasted work.
// =========================================================================
#define SW 131
__global__ __launch_bounds__(512, 1)
void warp_mean_kernel(const uint32_t* __restrict__ fh2,
                      const float* __restrict__ trans,
                      uint32_t* __restrict__ mh2)
{
    const int cp = blockIdx.x;      // 0..31
    const int bi = blockIdx.y;      // 0..9
    const int b  = bi / NA;
    const int i  = bi - b * NA;

    extern __shared__ uint32_t smu[];
    uint32_t* s_src = smu;              // SW*SW half2
    uint32_t* s_f   = smu + SW * SW;    // SW*SW half2

    const int tid = threadIdx.x;

    // border-only zeroing: 777 cells per plane, 2 planes
    //  v in [0,393): rows {0,129,130} x all 131 cols
    //  v in [393,777): rows 1..128 x cols {0,129,130}
    for (int v = tid; v < 2 * 777; v += 512) {
        int pl = (v >= 777) ? 1 : 0;
        int u  = v - pl * 777;
        int r, c;
        if (u < 393) {
            int rr = u / 131;               // 0,1,2
            r = (rr == 0) ? 0 : (128 + rr); // 0,129,130
            c = u - rr * 131;
        } else {
            int t = u - 393;
            r = 1 + t / 3;                  // 1..128
            int cc = t - (r - 1) * 3;       // 0,1,2
            c = (cc == 0) ? 0 : (128 + cc); // 0,129,130
        }
        smu[pl * (SW * SW) + r * SW + c] = 0u;
    }
    __syncthreads();

    float accx[32], accy[32];
#pragma unroll
    for (int k = 0; k < 32; k++) { accx[k] = 0.f; accy[k] = 0.f; }

    for (int j = 0; j < NA; j++) {
        if (j == i) continue;
        const float* tp = trans + (size_t)(bi * NA + j) * 16;
        const float t00 = tp[0], t01 = tp[1], t03 = tp[3];
        const float t10 = tp[4], t11 = tp[5], t13 = tp[7];

        const uint32_t* src = fh2 + (((size_t)(b * NA + j) * NCP + cp) << 14);
#pragma unroll
        for (int v = tid; v < HW / 4; v += 512) {
            uint4 x = ((const uint4*)src)[v];
            int r  = v >> 5;
            int c4 = (v & 31) << 2;
            uint32_t* d = s_src + (r + 1) * SW + c4 + 1;
            d[0] = x.x; d[1] = x.y; d[2] = x.z; d[3] = x.w;
        }
        __syncthreads();

        // ---- pass 1: rotation resample (half2 lerp) ----
#pragma unroll 4
        for (int k = 0; k < 32; k++) {
            int p = tid + (k << 9);
            int h = p >> 7, w = p & 127;
            float wf = (float)w - 63.5f;
            float hf = (float)h - 63.5f;
            float px = fmaf(t00, wf, fmaf(t01, hf, 63.5f));
            float py = fmaf(t10, wf, fmaf(t11, hf, 63.5f));
            px = fminf(fmaxf(px, -1.f), 128.f);
            py = fminf(fmaxf(py, -1.f), 128.f);
            float x0f = floorf(px), y0f = floorf(py);
            float fx = px - x0f, fy = py - y0f;
            int base = ((int)y0f + 1) * SW + (int)x0f + 1;
            __half2 a00 = *(__half2*)&s_src[base];
            __half2 a10 = *(__half2*)&s_src[base + 1];
            __half2 a01 = *(__half2*)&s_src[base + SW];
            __half2 a11 = *(__half2*)&s_src[base + SW + 1];
            __half2 hfx = __float2half2_rn(fx);
            __half2 hgx = __float2half2_rn(1.f - fx);
            __half2 hfy = __float2half2_rn(fy);
            __half2 hgy = __float2half2_rn(1.f - fy);
            __half2 t0 = __hfma2(a10, hfx, __hmul2(a00, hgx));
            __half2 t1 = __hfma2(a11, hfx, __hmul2(a01, hgx));
            __half2 r  = __hfma2(t1, hfy, __hmul2(t0, hgy));
            s_f[(h + 1) * SW + w + 1] = *(uint32_t*)&r;
        }
        __syncthreads();

        // ---- pass 2: constant-shift translate resample, fp32 accumulate ----
        const float tx = 2.f * t03;
        const float ty = -2.f * t13;
#pragma unroll 4
        for (int k = 0; k < 32; k++) {
            int p = tid + (k << 9);
            int h = p >> 7, w = p & 127;
            float px = fminf(fmaxf((float)w + tx, -1.f), 128.f);
            float py = fminf(fmaxf((float)h + ty, -1.f), 128.f);
            float x0f = floorf(px), y0f = floorf(py);
            float fx = px - x0f, fy = py - y0f;
            int base = ((int)y0f + 1) * SW + (int)x0f + 1;
            __half2 a00 = *(__half2*)&s_f[base];
            __half2 a10 = *(__half2*)&s_f[base + 1];
            __half2 a01 = *(__half2*)&s_f[base + SW];
            __half2 a11 = *(__half2*)&s_f[base + SW + 1];
            __half2 hfx = __float2half2_rn(fx);
            __half2 hgx = __float2half2_rn(1.f - fx);
            __half2 hfy = __float2half2_rn(fy);
            __half2 hgy = __float2half2_rn(1.f - fy);
            __half2 t0 = __hfma2(a10, hfx, __hmul2(a00, hgx));
            __half2 t1 = __hfma2(a11, hfx, __hmul2(a01, hgx));
            __half2 r  = __hfma2(t1, hfy, __hmul2(t0, hgy));
            float2 rf = __half22float2(r);
            accx[k] += rf.x;
            accy[k] += rf.y;
        }
        __syncthreads();
    }

    uint32_t* out = mh2 + (((size_t)bi * NCP + cp) << 14);
#pragma unroll
    for (int k = 0; k < 32; k++) {
        __half2 h = __floats2half2_rn(accx[k] * 0.25f, accy[k] * 0.25f);
        out[tid + (k << 9)] = *(uint32_t*)&h;
    }
}

// =========================================================================
// Kernel 2: conv implicit GEMM (fp16 mma.sync) + fused ConvGRU gating.
// (R15 exactly: static A band + per-group B streaming + named barriers +
// fast-exp epilogue; tensor 55.2%.)
// =========================================================================
#define BANDW    130
#define BAND_PXB 256u                       // bytes per (hh,ww): 64 cp * 4
#define BAND_HS  (BANDW * BAND_PXB)         // 33280
#define BAND_SZ  (4u * BAND_HS)             // 133120
#define BROW     144u                       // 128B of halves + 16B pad
#define BTILE    (192u * BROW)              // 27648
#define NSLOT    3
#define CONV_SMEM ((int)(BAND_SZ + NSLOT * BTILE))   // 216064

__global__ __launch_bounds__(512, 1)
void conv_gate_kernel(const uint32_t* __restrict__ fh2,
                      const uint32_t* __restrict__ mh2,
                      const __half* __restrict__ wt,
                      const float* __restrict__ bx,
                      const float* __restrict__ bh,
                      float* __restrict__ outf,
                      uint32_t* __restrict__ outh2,
                      int final_iter)
{
    extern __shared__ char smemraw[];
    const uint32_t sbase = smem_to_u32(smemraw);
    const uint32_t bring = sbase + BAND_SZ;

    const int tid  = threadIdx.x;
    const int wid  = tid >> 5;
    const int lane = tid & 31;
    const int rp = blockIdx.x;        // row pair 0..63
    const int n  = blockIdx.y;        // image 0..9
    const int h0 = rp * 2;

    const int wm = wid & 3;           // m-warp: rows (wm>>1), w-half (wm&1)
    const int wn = wid >> 2;          // n-warp: channel block wn*16 (group id)
    const int gt = tid & 127;         // thread id within warp group

    float c[4][6][4];
#pragma unroll
    for (int mt = 0; mt < 4; mt++)
#pragma unroll
        for (int nt = 0; nt < 6; nt++)
#pragma unroll
            for (int r = 0; r < 4; r++) c[mt][nt][r] = 0.f;

    // ---------------- band fill (once) ----------------
    {
        int bhh = tid >> 7;                 // 0..3
        int ww  = ((tid >> 6) & 1) ? 129 : 0;
        int cc  = tid & 63;
        uint32_t dst = sbase + bhh * BAND_HS + (uint32_t)ww * BAND_PXB
                     + ((uint32_t)((cc >> 2) ^ (ww & 7)) << 4) + ((cc & 3) << 2);
        STS32(dst, 0u);
    }
    {
        const int wwt  = tid & 127;         // pixel w (=ww-1)
        const int csub = tid >> 7;          // 0..3
        const int ww   = wwt + 1;
        const uint32_t wsw = (uint32_t)(ww & 7);
#pragma unroll
        for (int bhh = 0; bhh < 4; bhh++) {
            const int gh  = h0 - 1 + bhh;
            const bool hok = ((unsigned)gh < 128u);
            const int ghc = hok ? gh : 0;
            const uint32_t sz = hok ? 4u : 0u;
            const uint32_t dst0 = sbase + bhh * BAND_HS + (uint32_t)ww * BAND_PXB;
#pragma unroll
            for (int cg = 0; cg < 16; cg++) {
                const int cc = cg * 4 + csub;          // 0..63
                const uint32_t* src = (cc < 32)
                    ? (fh2 + (((size_t)n * NCP + cc)      << 14))
                    : (mh2 + (((size_t)n * NCP + cc - 32) << 14));
                uint32_t dst = dst0 + (((uint32_t)cg ^ wsw) << 4) + (csub << 2);
                CP_ASYNC4(dst, src + (ghc << 7) + wwt, sz);
            }
        }
    }

    // ---------------- B stage loader: group wn loads its own 48 rows ----
    auto prefetch_B = [&](int s, uint32_t slot) {
        const int tap = s >> 1;
        const int hs  = s & 1;
        const __half* wb = wt + tap * 128 + hs * 64;
#pragma unroll
        for (int i = 0; i < 3; i++) {
            int idx = gt + (i << 7);        // 0..383 = 48 rows * 8 chunks
            int ol = idx >> 3, q = idx & 7;
            int o  = wn * 48 + ol;
            CP_ASYNC16(slot + o * BROW + q * 16, wb + (size_t)o * KK + q * 8);
        }
    };

    // ---------------- MMA stage ----------------
    const int lm = lane & 15;
    const int lk = lane >> 4;
    const int b_row  = (lane & 7) + ((lane >> 4) << 3);
    const int b_koff = ((lane >> 3) & 1) * 16;

    auto do_mma = [&](int s, uint32_t slot) {
        const int tap = s >> 1;
        const int ty  = tap / 3;
        const int dy  = ty - 1;
        const int dx  = tap - ty * 3 - 1;
        const int cb  = (s & 1) * 8;        // chunk base within pixel entry

        const int ww  = (wm & 1) * 64 + lm + dx + 1;
        const uint32_t w7 = (uint32_t)(ww & 7);
        const uint32_t abase = sbase
            + (uint32_t)((wm >> 1) + dy + 1) * BAND_HS
            + (uint32_t)ww * BAND_PXB;
        const uint32_t bb = slot + (uint32_t)(wn * 48 + b_row) * BROW + b_koff;

#pragma unroll
        for (int ks = 0; ks < 4; ks++) {
            uint32_t bf[3][4];
#pragma unroll
            for (int bt = 0; bt < 3; bt++)
                LDMATRIX_X4(bf[bt][0], bf[bt][1], bf[bt][2], bf[bt][3],
                            bb + bt * (16 * BROW) + ks * 32);
            const uint32_t koff =
                ((uint32_t)(cb + ks * 2 + lk) ^ w7) << 4;
            // A fragments double-buffered across mt
            uint32_t a[2][4];
            LDMATRIX_X4(a[0][0], a[0][1], a[0][2], a[0][3], abase + koff);
#pragma unroll
            for (int mt = 0; mt < 4; mt++) {
                const int cur = mt & 1, nxt = cur ^ 1;
                if (mt < 3)
                    LDMATRIX_X4(a[nxt][0], a[nxt][1], a[nxt][2], a[nxt][3],
                                abase + (mt + 1) * (16 * 256) + koff);
#pragma unroll
                for (int nt = 0; nt < 6; nt++)
                    MMA16816(c[mt][nt], a[cur],
                             bf[nt >> 1][(nt & 1) * 2],
                             bf[nt >> 1][(nt & 1) * 2 + 1]);
            }
        }
    };

    // ---------------- pipeline: band + 2-deep per-group B prefetch ------
    prefetch_B(0, bring);                 CP_COMMIT();   // g0 = band + B0
    prefetch_B(1, bring + BTILE);         CP_COMMIT();   // g1 = B1
    CP_WAIT_GROUP(1);
    __syncthreads();                      // band visible CTA-wide; B0 done

    for (int s = 0; s < 18; s++) {
        if (s + 2 < 18)
            prefetch_B(s + 2, bring + (uint32_t)((s + 2) % 3) * BTILE);
        CP_COMMIT();                      // uniform per-thread group count
        do_mma(s, bring + (uint32_t)(s % 3) * BTILE);
        CP_WAIT_GROUP(1);
        BAR_SYNC(1 + wn, 128);            // group-scope rendezvous only
    }

    // ---------------- epilogue: gate in registers, store ----------------
    const int cw = lane >> 2;
    const int cn = (lane & 3) * 2;        // even channel of the owned pair
    const int r  = wm >> 1;
    const int h  = h0 + r;
    const int wbase = (wm & 1) * 64;
#pragma unroll
    for (int half = 0; half < 2; half++) {
        const int ch0 = wn * 16 + half * 8 + cn;      // even
        float bxr[2], bxz[2], bxn[2], bhn[2];
#pragma unroll
        for (int q = 0; q < 2; q++) {
            const int ch = ch0 + q;
            bxr[q] = bx[ch]       + bh[ch];
            bxz[q] = bx[ch + 64]  + bh[ch + 64];
            bxn[q] = bx[ch + 128];
            bhn[q] = bh[ch + 128];
        }
#pragma unroll
        for (int mt = 0; mt < 4; mt++) {
#pragma unroll
            for (int rr = 0; rr < 2; rr++) {
                const int w = wbase + mt * 16 + cw + rr * 8;
                float o01[2];
#pragma unroll
                for (int q = 0; q < 2; q++) {
                    const int k = rr * 2 + q;
                    float xr = c[mt][0 + half][k];
                    float xz = c[mt][2 + half][k];
                    float xn = c[mt][4 + half][k];
                    float rg = __fdividef(1.f, 1.f + __expf(-(xr + bxr[q])));
                    float zg = __fdividef(1.f, 1.f + __expf(-(xz + bxz[q])));
                    float e2 = __expf(-2.f * (xn + bxn[q] + rg * bhn[q]));
                    float ng = __fdividef(1.f - e2, 1.f + e2);
                    o01[q] = (1.f - zg) * ng;
                }
                if (final_iter) {
                    outf[(((size_t)n * NC + ch0)     << 14) + (h << 7) + w] = o01[0];
                    outf[(((size_t)n * NC + ch0 + 1) << 14) + (h << 7) + w] = o01[1];
                } else {
                    __half2 hp = __floats2half2_rn(o01[0], o01[1]);
                    outh2[(((size_t)n * NCP + (ch0 >> 1)) << 14) + (h << 7) + w]
                        = *(uint32_t*)&hp;
                }
            }
        }
    }
}

// =========================================================================
extern "C" void kernel_launch(void* const* d_in, const int* in_sizes, int n_in,
                              void* d_out, int out_size)
{
    const float* feats = (const float*)d_in[0];   // [2,5,64,128,128]
    const float* trans = (const float*)d_in[1];   // [2,5,5,4,4]
    const float* wx    = (const float*)d_in[2];   // [192,128,3,3]
    const float* bx    = (const float*)d_in[4];   // [192]
    const float* bh    = (const float*)d_in[5];   // [192]
    float* out = (float*)d_out;                   // [2,5,64,128,128]

    uint32_t *pa, *pb, *pm;
    __half* pw;
    cudaGetSymbolAddress((void**)&pa, g_fh2a);
    cudaGetSymbolAddress((void**)&pb, g_fh2b);
    cudaGetSymbolAddress((void**)&pm, g_mh2);
    cudaGetSymbolAddress((void**)&pw, g_wt);

    const int smem1 = 2 * SW * SW * (int)sizeof(uint32_t);   // 137288
    cudaFuncSetAttribute(warp_mean_kernel,
                         cudaFuncAttributeMaxDynamicSharedMemorySize, smem1);
    cudaFuncSetAttribute(conv_gate_kernel,
                         cudaFuncAttributeMaxDynamicSharedMemorySize, CONV_SMEM);

    prep_kernel<<<CVT_BLOCKS + WT_BLOCKS, 256>>>(feats, pa, wx, pw);

    for (int it = 0; it < 2; it++) {
        const uint32_t* fin = (it == 0) ? pa : pb;
        warp_mean_kernel<<<dim3(NCP, BA), 512, smem1>>>(fin, trans, pm);
        conv_gate_kernel<<<dim3(HH / 2, BA), 512, CONV_SMEM>>>(
            fin, pm, pw, bx, bh, out, pb, (it == 1) ? 1 : 0);
    }
}